// round 5
// baseline (speedup 1.0000x reference)
#include <cuda_runtime.h>
#include <cuda_bf16.h>
#include <math.h>
#include <stdint.h>

#define EMB     1024
#define NHEAD   16
#define HDIM    64
#define NBATCH  4
#define SEQ     8192
#define MTOK    (NBATCH * SEQ)          // 32768

// ---------------- scratch (device globals; allocation-free) ----------------
__device__ float g_Q[(size_t)MTOK * EMB];
__device__ float g_K[(size_t)MTOK * EMB];
__device__ float g_V[(size_t)MTOK * EMB];
__device__ __nv_bfloat16 g_xhi[(size_t)MTOK * EMB];
__device__ __nv_bfloat16 g_xlo[(size_t)MTOK * EMB];
__device__ __nv_bfloat16 g_yhi[(size_t)MTOK * EMB];
__device__ __nv_bfloat16 g_ylo[(size_t)MTOK * EMB];
__device__ __nv_bfloat16 g_whi[4][(size_t)EMB * EMB];
__device__ __nv_bfloat16 g_wlo[4][(size_t)EMB * EMB];

static __device__ __forceinline__ uint32_t smem_u32(const void* p) {
    uint32_t a;
    asm("{ .reg .u64 t; cvta.to.shared.u64 t, %1; cvt.u32.u64 %0, t; }" : "=r"(a) : "l"(p));
    return a;
}

static __device__ __forceinline__ void ldsm4(uint32_t* r, uint32_t addr) {
    asm volatile("ldmatrix.sync.aligned.m8n8.x4.shared.b16 {%0,%1,%2,%3}, [%4];"
                 : "=r"(r[0]), "=r"(r[1]), "=r"(r[2]), "=r"(r[3]) : "r"(addr));
}

static __device__ __forceinline__ void mma16816(float* d, const uint32_t* a,
                                                uint32_t b0, uint32_t b1) {
    asm volatile(
        "mma.sync.aligned.m16n8k16.row.col.f32.bf16.bf16.f32 "
        "{%0,%1,%2,%3}, {%4,%5,%6,%7}, {%8,%9}, {%0,%1,%2,%3};"
        : "+f"(d[0]), "+f"(d[1]), "+f"(d[2]), "+f"(d[3])
        : "r"(a[0]), "r"(a[1]), "r"(a[2]), "r"(a[3]), "r"(b0), "r"(b1));
}

// ---------------- fp32 -> bf16 hi/lo split ----------------
__global__ __launch_bounds__(256)
void split_fp32(const float* __restrict__ in, __nv_bfloat16* __restrict__ hi,
                __nv_bfloat16* __restrict__ lo, int n4)
{
    int i = blockIdx.x * blockDim.x + threadIdx.x;
    if (i >= n4) return;
    float4 v = ((const float4*)in)[i];
    float f[4] = {v.x, v.y, v.z, v.w};
    __nv_bfloat16 h[4], l[4];
    #pragma unroll
    for (int k = 0; k < 4; ++k) {
        h[k] = __float2bfloat16(f[k]);
        l[k] = __float2bfloat16(f[k] - __bfloat162float(h[k]));
    }
    __nv_bfloat162* hp = (__nv_bfloat162*)hi;
    __nv_bfloat162* lp = (__nv_bfloat162*)lo;
    hp[2 * i + 0] = __nv_bfloat162(h[0], h[1]);
    hp[2 * i + 1] = __nv_bfloat162(h[2], h[3]);
    lp[2 * i + 0] = __nv_bfloat162(l[0], l[1]);
    lp[2 * i + 1] = __nv_bfloat162(l[2], l[3]);
}

// ---------------- HMMA GEMM: C[m,n] = bias[n] + sum_k A[m,k]*W[n,k] ----------------
// bf16 3-term split (Ah*Bh + Ah*Bl + Al*Bh), fp32 accumulate.
// CTA 128(M) x 256(N), 8 warps (2Mx4N), warp tile 64x64. BK=32, 3-stage cp.async.
// Smem row: 128B = [hi: 32 bf16][lo: 32 bf16], XOR-swizzled in 16B chunks.
#define BKG         32
#define NKC         (EMB / BKG)        // 32
#define A_TILE_B    16384              // 128 rows x 128B
#define B_TILE_B    32768              // 256 rows x 128B
#define STAGE_B     (A_TILE_B + B_TILE_B)   // 48 KB
#define NSTG        3
#define GEMM_SMEM   (NSTG * STAGE_B)   // 144 KB

__global__ __launch_bounds__(256, 1)
void gemm_mma(const __nv_bfloat16* __restrict__ Ahi, const __nv_bfloat16* __restrict__ Alo,
              const __nv_bfloat16* __restrict__ Bhi, const __nv_bfloat16* __restrict__ Blo,
              const float* __restrict__ bias, float* __restrict__ C)
{
    extern __shared__ __align__(128) char dsm[];
    const uint32_t sbase = smem_u32(dsm);

    const int tid  = threadIdx.x;
    const int wid  = tid >> 5;
    const int lane = tid & 31;
    const int wm   = wid >> 2;          // 0..1
    const int wn   = wid & 3;           // 0..3
    const int bn   = blockIdx.x, bm = blockIdx.y;

    const char* aHi = (const char*)Ahi + (size_t)bm * 128 * 2048;
    const char* aLo = (const char*)Alo + (size_t)bm * 128 * 2048;
    const char* bHi = (const char*)Bhi + (size_t)bn * 256 * 2048;
    const char* bLo = (const char*)Blo + (size_t)bn * 256 * 2048;

    const int lrow0 = tid >> 3;        // 0..31
    const int lc    = tid & 7;         // 16B chunk id: 0-3 hi, 4-7 lo
    const char* aSrc = (lc < 4 ? aHi : aLo);
    const char* bSrc = (lc < 4 ? bHi : bLo);
    const int   srcCol = (lc & 3) * 16;

    #define LOAD_STAGE(kc_, slot_) do {                                           \
        uint32_t sb_ = sbase + (slot_) * STAGE_B;                                 \
        _Pragma("unroll")                                                         \
        for (int i_ = 0; i_ < 4; ++i_) {                                          \
            int row_ = lrow0 + i_ * 32;                                           \
            uint32_t dst_ = sb_ + row_ * 128 + ((lc ^ (row_ & 7)) << 4);          \
            const char* sa_ = aSrc + (size_t)row_ * 2048 + (kc_) * 64 + srcCol;   \
            asm volatile("cp.async.cg.shared.global [%0], [%1], 16;"              \
                         :: "r"(dst_), "l"(sa_));                                 \
        }                                                                         \
        _Pragma("unroll")                                                         \
        for (int i_ = 0; i_ < 8; ++i_) {                                          \
            int row_ = lrow0 + i_ * 32;                                           \
            uint32_t dst_ = sb_ + A_TILE_B + row_ * 128 + ((lc ^ (row_ & 7)) << 4);\
            const char* sb2_ = bSrc + (size_t)row_ * 2048 + (kc_) * 64 + srcCol;  \
            asm volatile("cp.async.cg.shared.global [%0], [%1], 16;"              \
                         :: "r"(dst_ + 0), "l"(sb2_));                            \
        }                                                                         \
        asm volatile("cp.async.commit_group;");                                   \
    } while (0)

    float acc[4][8][4];
    #pragma unroll
    for (int i = 0; i < 4; ++i)
        #pragma unroll
        for (int j = 0; j < 8; ++j)
            #pragma unroll
            for (int k = 0; k < 4; ++k) acc[i][j][k] = 0.0f;

    LOAD_STAGE(0, 0);
    LOAD_STAGE(1, 1);

    // ldmatrix per-lane invariants
    const int llo = lane & 15;          // row within 16
    const int lhi = lane >> 4;          // k-half chunk select
    const int r7  = llo & 7;
    uint32_t aRow[4], bRow[4];
    #pragma unroll
    for (int mi = 0; mi < 4; ++mi) aRow[mi] = (wm * 64 + mi * 16 + llo) * 128;
    #pragma unroll
    for (int g = 0; g < 4; ++g)    bRow[g] = A_TILE_B + (wn * 64 + g * 16 + llo) * 128;

    // one 64x64 x k16 block: 4 mi x 4 g (each g = two n8 frags)
    #define MMA_BLOCK(af_, bf_) do {                                              \
        _Pragma("unroll")                                                         \
        for (int mi_ = 0; mi_ < 4; ++mi_)                                         \
            _Pragma("unroll")                                                     \
            for (int g_ = 0; g_ < 4; ++g_) {                                      \
                mma16816(acc[mi_][2 * g_ + 0], (af_)[mi_],                        \
                         (bf_)[g_][0], (bf_)[g_][2]);                             \
                mma16816(acc[mi_][2 * g_ + 1], (af_)[mi_],                        \
                         (bf_)[g_][1], (bf_)[g_][3]);                             \
            }                                                                     \
    } while (0)

    for (int kc = 0; kc < NKC; ++kc) {
        asm volatile("cp.async.wait_group 1;" ::: "memory");
        __syncthreads();
        if (kc + 2 < NKC) LOAD_STAGE(kc + 2, (kc + 2) % NSTG);
        else              asm volatile("cp.async.commit_group;");   // keep wait-count aligned

        uint32_t st = sbase + (kc % NSTG) * STAGE_B;
        #pragma unroll
        for (int kh = 0; kh < 2; ++kh) {
            uint32_t af[4][4], bfH[4][4], bfL[4][4];
            const int chH = 2 * kh + lhi;
            const int chL = 4 + 2 * kh + lhi;
            const uint32_t xH = (uint32_t)((chH ^ r7) << 4);
            const uint32_t xL = (uint32_t)((chL ^ r7) << 4);

            #pragma unroll
            for (int mi = 0; mi < 4; ++mi) ldsm4(af[mi], st + aRow[mi] + xH);   // Ah
            #pragma unroll
            for (int g = 0; g < 4; ++g)    ldsm4(bfH[g], st + bRow[g] + xH);    // Bh
            #pragma unroll
            for (int g = 0; g < 4; ++g)    ldsm4(bfL[g], st + bRow[g] + xL);    // Bl
            MMA_BLOCK(af, bfH);                                                  // hh
            MMA_BLOCK(af, bfL);                                                  // hl
            #pragma unroll
            for (int mi = 0; mi < 4; ++mi) ldsm4(af[mi], st + aRow[mi] + xL);   // Al
            MMA_BLOCK(af, bfH);                                                  // lh
        }
    }

    // ---- epilogue: direct fp32 stores + bias ----
    const int qr = lane >> 2;           // 0..7
    const int qc = 2 * (lane & 3);      // 0,2,4,6
    #pragma unroll
    for (int nj = 0; nj < 8; ++nj) {
        const int cidx = bn * 256 + wn * 64 + nj * 8 + qc;
        const float2 bv = *(const float2*)&bias[cidx];
        #pragma unroll
        for (int mi = 0; mi < 4; ++mi) {
            const int r = bm * 128 + wm * 64 + mi * 16 + qr;
            float2 v0 = make_float2(acc[mi][nj][0] + bv.x, acc[mi][nj][1] + bv.y);
            float2 v1 = make_float2(acc[mi][nj][2] + bv.x, acc[mi][nj][3] + bv.y);
            *(float2*)&C[(size_t)r * EMB + cidx]       = v0;
            *(float2*)&C[(size_t)(r + 8) * EMB + cidx] = v1;
        }
    }
}

// ---------------- per-token 16x16 head-gram attention + scatter ----------------
// Writes bf16 hi/lo split of Y directly (fused with the former split kernel).
__global__ __launch_bounds__(256)
void attn_kernel(const float* __restrict__ Q, const float* __restrict__ K,
                 const float* __restrict__ V, __nv_bfloat16* __restrict__ Yhi,
                 __nv_bfloat16* __restrict__ Ylo)
{
    __shared__ float qs[EMB];
    __shared__ float ksT[HDIM][NHEAD + 1];   // transposed: conflict-free over j
    __shared__ float vs[EMB];
    __shared__ float Ash[16][17];

    const int t   = blockIdx.x;
    const int tid = threadIdx.x;
    const size_t base = (size_t)t * EMB;

    ((float4*)qs)[tid] = ((const float4*)(Q + base))[tid];
    float4 kv = ((const float4*)(K + base))[tid];
    {
        int e0 = tid * 4;
        int kj = e0 >> 6;
        int kd = e0 & 63;
        ksT[kd + 0][kj] = kv.x;
        ksT[kd + 1][kj] = kv.y;
        ksT[kd + 2][kj] = kv.z;
        ksT[kd + 3][kj] = kv.w;
    }
    ((float4*)vs)[tid] = ((const float4*)(V + base))[tid];
    __syncthreads();

    const int i = tid >> 4;
    const int j = tid & 15;
    float e = 0.0f;
    #pragma unroll 16
    for (int d = 0; d < HDIM; ++d)
        e = fmaf(qs[i * HDIM + d], ksT[d][j], e);
    e *= 0.03125f;   // 1/sqrt(1024)

    float m = e;
    #pragma unroll
    for (int off = 8; off > 0; off >>= 1)
        m = fmaxf(m, __shfl_xor_sync(0xffffffffu, m, off));
    float p = expf(e - m);
    float ssum = p;
    #pragma unroll
    for (int off = 8; off > 0; off >>= 1)
        ssum += __shfl_xor_sync(0xffffffffu, ssum, off);
    Ash[i][j] = p / ssum;
    __syncthreads();

    const int i2 = tid >> 4;
    const int dq = tid & 15;
    float4 o = make_float4(0.f, 0.f, 0.f, 0.f);
    #pragma unroll
    for (int jj = 0; jj < 16; ++jj) {
        float a = Ash[i2][jj];
        float4 vv = *(const float4*)(vs + jj * HDIM + dq * 4);
        o.x = fmaf(a, vv.x, o.x);
        o.y = fmaf(a, vv.y, o.y);
        o.z = fmaf(a, vv.z, o.z);
        o.w = fmaf(a, vv.w, o.w);
    }

    const int n = t >> 13;
    const int s = t & 8191;
    const int orow = i2 * 512 + (s >> 4);
    const int ocol = ((s & 15) << 6) + (dq << 2);
    const size_t off = ((size_t)n * SEQ + orow) * EMB + ocol;

    float f[4] = {o.x, o.y, o.z, o.w};
    __nv_bfloat16 h[4], l[4];
    #pragma unroll
    for (int k = 0; k < 4; ++k) {
        h[k] = __float2bfloat16(f[k]);
        l[k] = __float2bfloat16(f[k] - __bfloat162float(h[k]));
    }
    __nv_bfloat162 h01, h23, l01, l23;
    h01.x = h[0]; h01.y = h[1]; h23.x = h[2]; h23.y = h[3];
    l01.x = l[0]; l01.y = l[1]; l23.x = l[2]; l23.y = l[3];
    uint2 hv = make_uint2(*(uint32_t*)&h01, *(uint32_t*)&h23);
    uint2 lv = make_uint2(*(uint32_t*)&l01, *(uint32_t*)&l23);
    *(uint2*)(Yhi + off) = hv;
    *(uint2*)(Ylo + off) = lv;
}

// ---------------- launch ----------------
extern "C" void kernel_launch(void* const* d_in, const int* in_sizes, int n_in,
                              void* d_out, int out_size)
{
    const float* x  = (const float*)d_in[0];
    const float* W[4] = {(const float*)d_in[1], (const float*)d_in[2],
                         (const float*)d_in[3], (const float*)d_in[4]};
    const float* bq = (const float*)d_in[5];
    const float* bk = (const float*)d_in[6];
    const float* bv = (const float*)d_in[7];
    const float* bo = (const float*)d_in[8];
    float* out = (float*)d_out;

    float *pQ, *pK, *pV;
    __nv_bfloat16 *xhi, *xlo, *yhi, *ylo, *whi, *wlo;
    cudaGetSymbolAddress((void**)&pQ,  g_Q);
    cudaGetSymbolAddress((void**)&pK,  g_K);
    cudaGetSymbolAddress((void**)&pV,  g_V);
    cudaGetSymbolAddress((void**)&xhi, g_xhi);
    cudaGetSymbolAddress((void**)&xlo, g_xlo);
    cudaGetSymbolAddress((void**)&yhi, g_yhi);
    cudaGetSymbolAddress((void**)&ylo, g_ylo);
    cudaGetSymbolAddress((void**)&whi, g_whi);
    cudaGetSymbolAddress((void**)&wlo, g_wlo);

    cudaFuncSetAttribute(gemm_mma, cudaFuncAttributeMaxDynamicSharedMemorySize, GEMM_SMEM);

    const int n4x = MTOK * EMB / 4;
    const int n4w = EMB * EMB / 4;

    split_fp32<<<n4x / 256, 256>>>(x, xhi, xlo, n4x);
    for (int i = 0; i < 4; ++i)
        split_fp32<<<n4w / 256, 256>>>(W[i], whi + (size_t)i * EMB * EMB,
                                       wlo + (size_t)i * EMB * EMB, n4w);

    dim3 grid(EMB / 256, MTOK / 128);   // (4, 256)
    gemm_mma<<<grid, 256, GEMM_SMEM>>>(xhi, xlo, whi + 0 * (size_t)EMB * EMB,
                                       wlo + 0 * (size_t)EMB * EMB, bq, pQ);
    gemm_mma<<<grid, 256, GEMM_SMEM>>>(xhi, xlo, whi + 1 * (size_t)EMB * EMB,
                                       wlo + 1 * (size_t)EMB * EMB, bk, pK);
    gemm_mma<<<grid, 256, GEMM_SMEM>>>(xhi, xlo, whi + 2 * (size_t)EMB * EMB,
                                       wlo + 2 * (size_t)EMB * EMB, bv, pV);

    attn_kernel<<<MTOK, 256>>>(pQ, pK, pV, yhi, ylo);

    gemm_mma<<<grid, 256, GEMM_SMEM>>>(yhi, ylo, whi + 3 * (size_t)EMB * EMB,
                                       wlo + 3 * (size_t)EMB * EMB, bo, out);
}

// round 6
// speedup vs baseline: 1.4931x; 1.4931x over previous
#include <cuda_runtime.h>
#include <cuda_fp16.h>
#include <math.h>
#include <stdint.h>

#define EMB     1024
#define NHEAD   16
#define HDIM    64
#define NBATCH  4
#define SEQ     8192
#define MTOK    (NBATCH * SEQ)          // 32768

// ---------------- scratch (device globals; allocation-free) ----------------
__device__ float g_Q[(size_t)MTOK * EMB];
__device__ float g_K[(size_t)MTOK * EMB];
__device__ float g_V[(size_t)MTOK * EMB];
__device__ __half g_xh[(size_t)MTOK * EMB];
__device__ __half g_yh[(size_t)MTOK * EMB];
__device__ __half g_wh[4][(size_t)EMB * EMB];
__device__ __half g_wl[4][(size_t)EMB * EMB];

static __device__ __forceinline__ uint32_t smem_u32(const void* p) {
    uint32_t a;
    asm("{ .reg .u64 t; cvta.to.shared.u64 t, %1; cvt.u32.u64 %0, t; }" : "=r"(a) : "l"(p));
    return a;
}

static __device__ __forceinline__ void ldsm4(uint32_t* r, uint32_t addr) {
    asm volatile("ldmatrix.sync.aligned.m8n8.x4.shared.b16 {%0,%1,%2,%3}, [%4];"
                 : "=r"(r[0]), "=r"(r[1]), "=r"(r[2]), "=r"(r[3]) : "r"(addr));
}

static __device__ __forceinline__ void mma16816(float* d, const uint32_t* a,
                                                uint32_t b0, uint32_t b1) {
    asm volatile(
        "mma.sync.aligned.m16n8k16.row.col.f32.f16.f16.f32 "
        "{%0,%1,%2,%3}, {%4,%5,%6,%7}, {%8,%9}, {%0,%1,%2,%3};"
        : "+f"(d[0]), "+f"(d[1]), "+f"(d[2]), "+f"(d[3])
        : "r"(a[0]), "r"(a[1]), "r"(a[2]), "r"(a[3]), "r"(b0), "r"(b1));
}

// ---------------- fp32 -> fp16 round (A-side) ----------------
__global__ __launch_bounds__(256)
void to_half(const float* __restrict__ in, __half* __restrict__ out, int n4)
{
    int i = blockIdx.x * blockDim.x + threadIdx.x;
    if (i >= n4) return;
    float4 v = ((const float4*)in)[i];
    __half2 a = __floats2half2_rn(v.x, v.y);
    __half2 b = __floats2half2_rn(v.z, v.w);
    __half2* op = (__half2*)out;
    op[2 * i + 0] = a;
    op[2 * i + 1] = b;
}

// ---------------- fp32 -> fp16 hi/lo split (B-side weights) ----------------
__global__ __launch_bounds__(256)
void split_w(const float* __restrict__ in, __half* __restrict__ hi,
             __half* __restrict__ lo, int n4)
{
    int i = blockIdx.x * blockDim.x + threadIdx.x;
    if (i >= n4) return;
    float4 v = ((const float4*)in)[i];
    float f[4] = {v.x, v.y, v.z, v.w};
    __half h[4], l[4];
    #pragma unroll
    for (int k = 0; k < 4; ++k) {
        h[k] = __float2half_rn(f[k]);
        l[k] = __float2half_rn(f[k] - __half2float(h[k]));
    }
    __half2* hp = (__half2*)hi;
    __half2* lp = (__half2*)lo;
    hp[2 * i + 0] = __halves2half2(h[0], h[1]);
    hp[2 * i + 1] = __halves2half2(h[2], h[3]);
    lp[2 * i + 0] = __halves2half2(l[0], l[1]);
    lp[2 * i + 1] = __halves2half2(l[2], l[3]);
}

// ---------------- HMMA GEMM: C[m,n] = bias[n] + sum_k A[m,k]*W[n,k] ----------------
// fp16 2-term: A (single fp16) x (Bh + Bl), fp32 accumulate.
// CTA 128x128, 8 warps (2Mx4N), warp 64x32. BK=32, 3-stage cp.async.
// A smem: 128 rows x 64B (4 chunks), swizzle c ^ ((row>>1)&3).
// B smem: 128 rows x 128B = [hi 64B | lo 64B], swizzle c ^ (row&7).
#define BKG         32
#define NKC         (EMB / BKG)        // 32
#define A_TILE_B    8192               // 128 x 64B
#define B_TILE_B    16384              // 128 x 128B
#define STAGE_B     (A_TILE_B + B_TILE_B)   // 24 KB
#define NSTG        3
#define GEMM_SMEM   (NSTG * STAGE_B)   // 72 KB

__global__ __launch_bounds__(256, 2)
void gemm_mma(const __half* __restrict__ A, const __half* __restrict__ Bhi,
              const __half* __restrict__ Blo,
              const float* __restrict__ bias, float* __restrict__ C)
{
    extern __shared__ __align__(128) char dsm[];
    const uint32_t sbase = smem_u32(dsm);

    const int tid  = threadIdx.x;
    const int wid  = tid >> 5;
    const int lane = tid & 31;
    const int wm   = wid >> 2;          // 0..1
    const int wn   = wid & 3;           // 0..3
    const int bn   = blockIdx.x, bm = blockIdx.y;

    const char* aSrcB = (const char*)A   + (size_t)bm * 128 * 2048;
    const char* bHi   = (const char*)Bhi + (size_t)bn * 128 * 2048;
    const char* bLo   = (const char*)Blo + (size_t)bn * 128 * 2048;

    // A loader: c = tid&3, rows tid>>2 and +64 (2 chunks/thread)
    const int ac    = tid & 3;
    const int arow0 = tid >> 2;        // 0..63
    // B loader: lc 0-3 -> hi, 4-7 -> lo; rows tid>>3 + {0,32,64,96}
    const int lc    = tid & 7;
    const int lrow0 = tid >> 3;        // 0..31
    const char* bSrc = (lc < 4 ? bHi : bLo);
    const int  bCol  = (lc & 3) * 16;

    #define LOAD_STAGE(kc_, slot_) do {                                            \
        uint32_t sb_ = sbase + (slot_) * STAGE_B;                                  \
        _Pragma("unroll")                                                          \
        for (int i_ = 0; i_ < 2; ++i_) {                                           \
            int row_ = arow0 + i_ * 64;                                            \
            uint32_t dst_ = sb_ + row_ * 64 + ((ac ^ ((row_ >> 1) & 3)) << 4);     \
            const char* sa_ = aSrcB + (size_t)row_ * 2048 + (kc_) * 64 + ac * 16;  \
            asm volatile("cp.async.cg.shared.global [%0], [%1], 16;"               \
                         :: "r"(dst_), "l"(sa_));                                  \
        }                                                                          \
        _Pragma("unroll")                                                          \
        for (int i_ = 0; i_ < 4; ++i_) {                                           \
            int row_ = lrow0 + i_ * 32;                                            \
            uint32_t dst_ = sb_ + A_TILE_B + row_ * 128 + ((lc ^ (row_ & 7)) << 4);\
            const char* sb2_ = bSrc + (size_t)row_ * 2048 + (kc_) * 64 + bCol;     \
            asm volatile("cp.async.cg.shared.global [%0], [%1], 16;"               \
                         :: "r"(dst_), "l"(sb2_));                                 \
        }                                                                          \
        asm volatile("cp.async.commit_group;");                                    \
    } while (0)

    float acc[4][4][4];
    #pragma unroll
    for (int i = 0; i < 4; ++i)
        #pragma unroll
        for (int j = 0; j < 4; ++j)
            #pragma unroll
            for (int k = 0; k < 4; ++k) acc[i][j][k] = 0.0f;

    LOAD_STAGE(0, 0);
    LOAD_STAGE(1, 1);

    // ldmatrix per-lane invariants
    const int llo = lane & 15;          // row within 16
    const int lhi = lane >> 4;          // 16B half select
    const int r7  = llo & 7;
    const int sA  = (llo >> 1) & 3;     // A swizzle key (mi*16 preserves it)
    uint32_t aRow[4], bRow[2];
    #pragma unroll
    for (int mi = 0; mi < 4; ++mi) aRow[mi] = (wm * 64 + mi * 16 + llo) * 64;
    #pragma unroll
    for (int g = 0; g < 2; ++g)    bRow[g] = A_TILE_B + (wn * 32 + g * 16 + llo) * 128;

    #define MMA_BLOCK(af_, bf_) do {                                              \
        _Pragma("unroll")                                                         \
        for (int mi_ = 0; mi_ < 4; ++mi_)                                         \
            _Pragma("unroll")                                                     \
            for (int nj_ = 0; nj_ < 4; ++nj_)                                     \
                mma16816(acc[mi_][nj_], (af_)[mi_],                               \
                         (bf_)[nj_ >> 1][nj_ & 1], (bf_)[nj_ >> 1][2 + (nj_ & 1)]); \
    } while (0)

    for (int kc = 0; kc < NKC; ++kc) {
        asm volatile("cp.async.wait_group 1;" ::: "memory");
        __syncthreads();
        if (kc + 2 < NKC) LOAD_STAGE(kc + 2, (kc + 2) % NSTG);
        else              asm volatile("cp.async.commit_group;");   // keep wait-count aligned

        uint32_t st = sbase + (kc % NSTG) * STAGE_B;
        #pragma unroll
        for (int kh = 0; kh < 2; ++kh) {
            uint32_t af[4][4], bfH[2][4], bfL[2][4];
            const int ch  = 2 * kh + lhi;        // 16B chunk for this k16 half
            const uint32_t xA = (uint32_t)((ch ^ sA) << 4);
            const uint32_t xH = (uint32_t)((ch ^ r7) << 4);
            const uint32_t xL = (uint32_t)(((4 + ch) ^ r7) << 4);

            #pragma unroll
            for (int mi = 0; mi < 4; ++mi) ldsm4(af[mi], st + aRow[mi] + xA);   // A
            #pragma unroll
            for (int g = 0; g < 2; ++g)    ldsm4(bfH[g], st + bRow[g] + xH);    // Bh
            #pragma unroll
            for (int g = 0; g < 2; ++g)    ldsm4(bfL[g], st + bRow[g] + xL);    // Bl
            MMA_BLOCK(af, bfH);
            MMA_BLOCK(af, bfL);
        }
    }

    // ---- epilogue: direct fp32 stores + bias ----
    const int qr = lane >> 2;           // 0..7
    const int qc = 2 * (lane & 3);      // 0,2,4,6
    #pragma unroll
    for (int nj = 0; nj < 4; ++nj) {
        const int cidx = bn * 128 + wn * 32 + nj * 8 + qc;
        const float2 bv = *(const float2*)&bias[cidx];
        #pragma unroll
        for (int mi = 0; mi < 4; ++mi) {
            const int r = bm * 128 + wm * 64 + mi * 16 + qr;
            float2 v0 = make_float2(acc[mi][nj][0] + bv.x, acc[mi][nj][1] + bv.y);
            float2 v1 = make_float2(acc[mi][nj][2] + bv.x, acc[mi][nj][3] + bv.y);
            *(float2*)&C[(size_t)r * EMB + cidx]       = v0;
            *(float2*)&C[(size_t)(r + 8) * EMB + cidx] = v1;
        }
    }
}

// ---------------- per-token 16x16 head-gram attention + scatter ----------------
// Writes fp16 Y directly (A-side of final GEMM).
__global__ __launch_bounds__(256)
void attn_kernel(const float* __restrict__ Q, const float* __restrict__ K,
                 const float* __restrict__ V, __half* __restrict__ Yh)
{
    __shared__ float qs[EMB];
    __shared__ float ksT[HDIM][NHEAD + 1];
    __shared__ float vs[EMB];
    __shared__ float Ash[16][17];

    const int t   = blockIdx.x;
    const int tid = threadIdx.x;
    const size_t base = (size_t)t * EMB;

    ((float4*)qs)[tid] = ((const float4*)(Q + base))[tid];
    float4 kv = ((const float4*)(K + base))[tid];
    {
        int e0 = tid * 4;
        int kj = e0 >> 6;
        int kd = e0 & 63;
        ksT[kd + 0][kj] = kv.x;
        ksT[kd + 1][kj] = kv.y;
        ksT[kd + 2][kj] = kv.z;
        ksT[kd + 3][kj] = kv.w;
    }
    ((float4*)vs)[tid] = ((const float4*)(V + base))[tid];
    __syncthreads();

    const int i = tid >> 4;
    const int j = tid & 15;
    float e = 0.0f;
    #pragma unroll 16
    for (int d = 0; d < HDIM; ++d)
        e = fmaf(qs[i * HDIM + d], ksT[d][j], e);
    e *= 0.03125f;   // 1/sqrt(1024)

    float m = e;
    #pragma unroll
    for (int off = 8; off > 0; off >>= 1)
        m = fmaxf(m, __shfl_xor_sync(0xffffffffu, m, off));
    float p = expf(e - m);
    float ssum = p;
    #pragma unroll
    for (int off = 8; off > 0; off >>= 1)
        ssum += __shfl_xor_sync(0xffffffffu, ssum, off);
    Ash[i][j] = p / ssum;
    __syncthreads();

    const int i2 = tid >> 4;
    const int dq = tid & 15;
    float4 o = make_float4(0.f, 0.f, 0.f, 0.f);
    #pragma unroll
    for (int jj = 0; jj < 16; ++jj) {
        float a = Ash[i2][jj];
        float4 vv = *(const float4*)(vs + jj * HDIM + dq * 4);
        o.x = fmaf(a, vv.x, o.x);
        o.y = fmaf(a, vv.y, o.y);
        o.z = fmaf(a, vv.z, o.z);
        o.w = fmaf(a, vv.w, o.w);
    }

    const int n = t >> 13;
    const int s = t & 8191;
    const int orow = i2 * 512 + (s >> 4);
    const int ocol = ((s & 15) << 6) + (dq << 2);
    const size_t off = ((size_t)n * SEQ + orow) * EMB + ocol;

    __half2 h01 = __floats2half2_rn(o.x, o.y);
    __half2 h23 = __floats2half2_rn(o.z, o.w);
    uint2 hv = make_uint2(*(uint32_t*)&h01, *(uint32_t*)&h23);
    *(uint2*)(Yh + off) = hv;
}

// ---------------- launch ----------------
extern "C" void kernel_launch(void* const* d_in, const int* in_sizes, int n_in,
                              void* d_out, int out_size)
{
    const float* x  = (const float*)d_in[0];
    const float* W[4] = {(const float*)d_in[1], (const float*)d_in[2],
                         (const float*)d_in[3], (const float*)d_in[4]};
    const float* bq = (const float*)d_in[5];
    const float* bk = (const float*)d_in[6];
    const float* bv = (const float*)d_in[7];
    const float* bo = (const float*)d_in[8];
    float* out = (float*)d_out;

    float *pQ, *pK, *pV;
    __half *xh, *yh, *wh, *wl;
    cudaGetSymbolAddress((void**)&pQ, g_Q);
    cudaGetSymbolAddress((void**)&pK, g_K);
    cudaGetSymbolAddress((void**)&pV, g_V);
    cudaGetSymbolAddress((void**)&xh, g_xh);
    cudaGetSymbolAddress((void**)&yh, g_yh);
    cudaGetSymbolAddress((void**)&wh, g_wh);
    cudaGetSymbolAddress((void**)&wl, g_wl);

    cudaFuncSetAttribute(gemm_mma, cudaFuncAttributeMaxDynamicSharedMemorySize, GEMM_SMEM);

    const int n4x = MTOK * EMB / 4;
    const int n4w = EMB * EMB / 4;

    to_half<<<n4x / 256, 256>>>(x, xh, n4x);
    for (int i = 0; i < 4; ++i)
        split_w<<<n4w / 256, 256>>>(W[i], wh + (size_t)i * EMB * EMB,
                                    wl + (size_t)i * EMB * EMB, n4w);

    dim3 grid(EMB / 128, MTOK / 128);   // (8, 256)
    gemm_mma<<<grid, 256, GEMM_SMEM>>>(xh, wh + 0 * (size_t)EMB * EMB,
                                       wl + 0 * (size_t)EMB * EMB, bq, pQ);
    gemm_mma<<<grid, 256, GEMM_SMEM>>>(xh, wh + 1 * (size_t)EMB * EMB,
                                       wl + 1 * (size_t)EMB * EMB, bk, pK);
    gemm_mma<<<grid, 256, GEMM_SMEM>>>(xh, wh + 2 * (size_t)EMB * EMB,
                                       wl + 2 * (size_t)EMB * EMB, bv, pV);

    attn_kernel<<<MTOK, 256>>>(pQ, pK, pV, yh);

    gemm_mma<<<grid, 256, GEMM_SMEM>>>(yh, wh + 3 * (size_t)EMB * EMB,
                                       wl + 3 * (size_t)EMB * EMB, bo, out);
}

// round 7
// speedup vs baseline: 2.3785x; 1.5930x over previous
#include <cuda_runtime.h>
#include <cuda_fp16.h>
#include <math.h>
#include <stdint.h>

#define EMB     1024
#define NHEAD   16
#define HDIM    64
#define NBATCH  4
#define SEQ     8192
#define MTOK    (NBATCH * SEQ)          // 32768

// ---------------- scratch (device globals; allocation-free) ----------------
__device__ float g_Q[(size_t)MTOK * EMB];
__device__ float g_K[(size_t)MTOK * EMB];
__device__ float g_V[(size_t)MTOK * EMB];
__device__ __half g_xh[(size_t)MTOK * EMB];
__device__ __half g_yh[(size_t)MTOK * EMB];
__device__ __half g_wh[4][(size_t)EMB * EMB];

static __device__ __forceinline__ uint32_t smem_u32(const void* p) {
    uint32_t a;
    asm("{ .reg .u64 t; cvta.to.shared.u64 t, %1; cvt.u32.u64 %0, t; }" : "=r"(a) : "l"(p));
    return a;
}

static __device__ __forceinline__ void ldsm4(uint32_t* r, uint32_t addr) {
    asm volatile("ldmatrix.sync.aligned.m8n8.x4.shared.b16 {%0,%1,%2,%3}, [%4];"
                 : "=r"(r[0]), "=r"(r[1]), "=r"(r[2]), "=r"(r[3]) : "r"(addr));
}

static __device__ __forceinline__ void mma16816(float* d, const uint32_t* a,
                                                uint32_t b0, uint32_t b1) {
    asm volatile(
        "mma.sync.aligned.m16n8k16.row.col.f32.f16.f16.f32 "
        "{%0,%1,%2,%3}, {%4,%5,%6,%7}, {%8,%9}, {%0,%1,%2,%3};"
        : "+f"(d[0]), "+f"(d[1]), "+f"(d[2]), "+f"(d[3])
        : "r"(a[0]), "r"(a[1]), "r"(a[2]), "r"(a[3]), "r"(b0), "r"(b1));
}

// ---------------- fp32 -> fp16 round ----------------
__global__ __launch_bounds__(256)
void to_half(const float* __restrict__ in, __half* __restrict__ out, int n4)
{
    int i = blockIdx.x * blockDim.x + threadIdx.x;
    if (i >= n4) return;
    float4 v = ((const float4*)in)[i];
    __half2 a = __floats2half2_rn(v.x, v.y);
    __half2 b = __floats2half2_rn(v.z, v.w);
    __half2* op = (__half2*)out;
    op[2 * i + 0] = a;
    op[2 * i + 1] = b;
}

// ---------------- HMMA GEMM: C[m,n] = bias[n] + sum_k A[m,k]*W[n,k] ----------------
// Single-term fp16 x fp16, fp32 accumulate.
// CTA 128x128, 8 warps (2Mx4N), warp 64x32. BK=32, 3-stage cp.async.
// A/B smem tiles: 128 rows x 64B (4 x 16B chunks), swizzle c ^ ((row>>1)&3).
#define BKG         32
#define NKC         (EMB / BKG)        // 32
#define A_TILE_B    8192               // 128 x 64B
#define B_TILE_B    8192               // 128 x 64B
#define STAGE_B     (A_TILE_B + B_TILE_B)   // 16 KB
#define NSTG        3
#define GEMM_SMEM   (NSTG * STAGE_B)   // 48 KB

__global__ __launch_bounds__(256, 2)
void gemm_mma(const __half* __restrict__ A, const __half* __restrict__ B,
              const float* __restrict__ bias, float* __restrict__ C)
{
    extern __shared__ __align__(128) char dsm[];
    const uint32_t sbase = smem_u32(dsm);

    const int tid  = threadIdx.x;
    const int wid  = tid >> 5;
    const int lane = tid & 31;
    const int wm   = wid >> 2;          // 0..1
    const int wn   = wid & 3;           // 0..3
    const int bn   = blockIdx.x, bm = blockIdx.y;

    const char* aSrcB = (const char*)A + (size_t)bm * 128 * 2048;
    const char* bSrcB = (const char*)B + (size_t)bn * 128 * 2048;

    // loader: c = tid&3 (16B chunk), rows tid>>2 and +64 (2 chunks per matrix)
    const int ac    = tid & 3;
    const int arow0 = tid >> 2;        // 0..63

    #define LOAD_STAGE(kc_, slot_) do {                                            \
        uint32_t sb_ = sbase + (slot_) * STAGE_B;                                  \
        _Pragma("unroll")                                                          \
        for (int i_ = 0; i_ < 2; ++i_) {                                           \
            int row_ = arow0 + i_ * 64;                                            \
            uint32_t so_ = row_ * 64 + ((ac ^ ((row_ >> 1) & 3)) << 4);            \
            size_t  go_ = (size_t)row_ * 2048 + (kc_) * 64 + ac * 16;              \
            asm volatile("cp.async.cg.shared.global [%0], [%1], 16;"               \
                         :: "r"(sb_ + so_), "l"(aSrcB + go_));                     \
            asm volatile("cp.async.cg.shared.global [%0], [%1], 16;"               \
                         :: "r"(sb_ + A_TILE_B + so_), "l"(bSrcB + go_));          \
        }                                                                          \
        asm volatile("cp.async.commit_group;");                                    \
    } while (0)

    float acc[4][4][4];
    #pragma unroll
    for (int i = 0; i < 4; ++i)
        #pragma unroll
        for (int j = 0; j < 4; ++j)
            #pragma unroll
            for (int k = 0; k < 4; ++k) acc[i][j][k] = 0.0f;

    LOAD_STAGE(0, 0);
    LOAD_STAGE(1, 1);

    // ldmatrix per-lane invariants
    const int llo = lane & 15;          // row within 16
    const int lhi = lane >> 4;          // 16B half select
    const int sK  = (llo >> 1) & 3;     // swizzle key (tile row step 16 preserves it)
    uint32_t aRow[4], bRow[2];
    #pragma unroll
    for (int mi = 0; mi < 4; ++mi) aRow[mi] = (wm * 64 + mi * 16 + llo) * 64;
    #pragma unroll
    for (int g = 0; g < 2; ++g)    bRow[g] = A_TILE_B + (wn * 32 + g * 16 + llo) * 64;

    #define MMA_BLOCK(af_, bf_) do {                                              \
        _Pragma("unroll")                                                         \
        for (int mi_ = 0; mi_ < 4; ++mi_)                                         \
            _Pragma("unroll")                                                     \
            for (int nj_ = 0; nj_ < 4; ++nj_)                                     \
                mma16816(acc[mi_][nj_], (af_)[mi_],                               \
                         (bf_)[nj_ >> 1][nj_ & 1], (bf_)[nj_ >> 1][2 + (nj_ & 1)]); \
    } while (0)

    for (int kc = 0; kc < NKC; ++kc) {
        asm volatile("cp.async.wait_group 1;" ::: "memory");
        __syncthreads();
        if (kc + 2 < NKC) LOAD_STAGE(kc + 2, (kc + 2) % NSTG);
        else              asm volatile("cp.async.commit_group;");   // keep wait-count aligned

        uint32_t st = sbase + (kc % NSTG) * STAGE_B;
        #pragma unroll
        for (int kh = 0; kh < 2; ++kh) {
            uint32_t af[4][4], bf[2][4];
            const int ch = 2 * kh + lhi;                 // 16B chunk for this k16 half
            const uint32_t xk = (uint32_t)((ch ^ sK) << 4);

            #pragma unroll
            for (int mi = 0; mi < 4; ++mi) ldsm4(af[mi], st + aRow[mi] + xk);
            #pragma unroll
            for (int g = 0; g < 2; ++g)    ldsm4(bf[g], st + bRow[g] + xk);
            MMA_BLOCK(af, bf);
        }
    }

    // ---- epilogue: direct fp32 stores + bias ----
    const int qr = lane >> 2;           // 0..7
    const int qc = 2 * (lane & 3);      // 0,2,4,6
    #pragma unroll
    for (int nj = 0; nj < 4; ++nj) {
        const int cidx = bn * 128 + wn * 32 + nj * 8 + qc;
        const float2 bv = *(const float2*)&bias[cidx];
        #pragma unroll
        for (int mi = 0; mi < 4; ++mi) {
            const int r = bm * 128 + wm * 64 + mi * 16 + qr;
            float2 v0 = make_float2(acc[mi][nj][0] + bv.x, acc[mi][nj][1] + bv.y);
            float2 v1 = make_float2(acc[mi][nj][2] + bv.x, acc[mi][nj][3] + bv.y);
            *(float2*)&C[(size_t)r * EMB + cidx]       = v0;
            *(float2*)&C[(size_t)(r + 8) * EMB + cidx] = v1;
        }
    }
}

// ---------------- per-token 16x16 head-gram attention + scatter ----------------
// Writes fp16 Y directly (A-side of final GEMM).
__global__ __launch_bounds__(256)
void attn_kernel(const float* __restrict__ Q, const float* __restrict__ K,
                 const float* __restrict__ V, __half* __restrict__ Yh)
{
    __shared__ float qs[EMB];
    __shared__ float ksT[HDIM][NHEAD + 1];
    __shared__ float vs[EMB];
    __shared__ float Ash[16][17];

    const int t   = blockIdx.x;
    const int tid = threadIdx.x;
    const size_t base = (size_t)t * EMB;

    ((float4*)qs)[tid] = ((const float4*)(Q + base))[tid];
    float4 kv = ((const float4*)(K + base))[tid];
    {
        int e0 = tid * 4;
        int kj = e0 >> 6;
        int kd = e0 & 63;
        ksT[kd + 0][kj] = kv.x;
        ksT[kd + 1][kj] = kv.y;
        ksT[kd + 2][kj] = kv.z;
        ksT[kd + 3][kj] = kv.w;
    }
    ((float4*)vs)[tid] = ((const float4*)(V + base))[tid];
    __syncthreads();

    const int i = tid >> 4;
    const int j = tid & 15;
    float e = 0.0f;
    #pragma unroll 16
    for (int d = 0; d < HDIM; ++d)
        e = fmaf(qs[i * HDIM + d], ksT[d][j], e);
    e *= 0.03125f;   // 1/sqrt(1024)

    float m = e;
    #pragma unroll
    for (int off = 8; off > 0; off >>= 1)
        m = fmaxf(m, __shfl_xor_sync(0xffffffffu, m, off));
    float p = expf(e - m);
    float ssum = p;
    #pragma unroll
    for (int off = 8; off > 0; off >>= 1)
        ssum += __shfl_xor_sync(0xffffffffu, ssum, off);
    Ash[i][j] = p / ssum;
    __syncthreads();

    const int i2 = tid >> 4;
    const int dq = tid & 15;
    float4 o = make_float4(0.f, 0.f, 0.f, 0.f);
    #pragma unroll
    for (int jj = 0; jj < 16; ++jj) {
        float a = Ash[i2][jj];
        float4 vv = *(const float4*)(vs + jj * HDIM + dq * 4);
        o.x = fmaf(a, vv.x, o.x);
        o.y = fmaf(a, vv.y, o.y);
        o.z = fmaf(a, vv.z, o.z);
        o.w = fmaf(a, vv.w, o.w);
    }

    const int n = t >> 13;
    const int s = t & 8191;
    const int orow = i2 * 512 + (s >> 4);
    const int ocol = ((s & 15) << 6) + (dq << 2);
    const size_t off = ((size_t)n * SEQ + orow) * EMB + ocol;

    __half2 h01 = __floats2half2_rn(o.x, o.y);
    __half2 h23 = __floats2half2_rn(o.z, o.w);
    uint2 hv = make_uint2(*(uint32_t*)&h01, *(uint32_t*)&h23);
    *(uint2*)(Yh + off) = hv;
}

// ---------------- launch ----------------
extern "C" void kernel_launch(void* const* d_in, const int* in_sizes, int n_in,
                              void* d_out, int out_size)
{
    const float* x  = (const float*)d_in[0];
    const float* W[4] = {(const float*)d_in[1], (const float*)d_in[2],
                         (const float*)d_in[3], (const float*)d_in[4]};
    const float* bq = (const float*)d_in[5];
    const float* bk = (const float*)d_in[6];
    const float* bv = (const float*)d_in[7];
    const float* bo = (const float*)d_in[8];
    float* out = (float*)d_out;

    float *pQ, *pK, *pV;
    __half *xh, *yh, *wh;
    cudaGetSymbolAddress((void**)&pQ, g_Q);
    cudaGetSymbolAddress((void**)&pK, g_K);
    cudaGetSymbolAddress((void**)&pV, g_V);
    cudaGetSymbolAddress((void**)&xh, g_xh);
    cudaGetSymbolAddress((void**)&yh, g_yh);
    cudaGetSymbolAddress((void**)&wh, g_wh);

    cudaFuncSetAttribute(gemm_mma, cudaFuncAttributeMaxDynamicSharedMemorySize, GEMM_SMEM);

    const int n4x = MTOK * EMB / 4;
    const int n4w = EMB * EMB / 4;

    to_half<<<n4x / 256, 256>>>(x, xh, n4x);
    for (int i = 0; i < 4; ++i)
        to_half<<<n4w / 256, 256>>>(W[i], wh + (size_t)i * EMB * EMB, n4w);

    dim3 grid(EMB / 128, MTOK / 128);   // (8, 256)
    gemm_mma<<<grid, 256, GEMM_SMEM>>>(xh, wh + 0 * (size_t)EMB * EMB, bq, pQ);
    gemm_mma<<<grid, 256, GEMM_SMEM>>>(xh, wh + 1 * (size_t)EMB * EMB, bk, pK);
    gemm_mma<<<grid, 256, GEMM_SMEM>>>(xh, wh + 2 * (size_t)EMB * EMB, bv, pV);

    attn_kernel<<<MTOK, 256>>>(pQ, pK, pV, yh);

    gemm_mma<<<grid, 256, GEMM_SMEM>>>(yh, wh + 3 * (size_t)EMB * EMB, bo, out);
}